// round 2
// baseline (speedup 1.0000x reference)
#include <cuda_runtime.h>

#define TTOK 16384
#define DDIM 512
#define KCB  16384

// ---------------- scratch (device globals: no allocation allowed) ----------
__device__ float g_res[TTOK * DDIM];    // residual r (initially z)
__device__ float g_qsum[TTOK * DDIM];   // accumulated quantized vectors
__device__ float g_csq[KCB];            // ||c_k||^2
__device__ int   g_idx[TTOK];           // per-stage argmin indices

// Orderable-uint mapping for fp32: ascending uint <=> ascending float
__device__ __forceinline__ unsigned fkey(float f) {
    unsigned u = __float_as_uint(f);
    return (u & 0x80000000u) ? ~u : (u | 0x80000000u);
}

// XOR swizzle for [32 k][64 col] smem tiles: conflict-free transposed stores,
// float4-aligned reads (swizzle term is a multiple of 4).
#define SW(k, c) (((k) << 6) + ((c) ^ ((((k) >> 2) & 7) << 2)))

// ---------------- ||c||^2 -------------------------------------------------
__global__ void csq_kernel(const float* __restrict__ C) {
    int row  = blockIdx.x * 8 + (threadIdx.x >> 5);
    int lane = threadIdx.x & 31;
    const float4* p = (const float4*)(C + (size_t)row * DDIM);
    float s = 0.f;
#pragma unroll
    for (int i = 0; i < 4; i++) {
        float4 v = p[lane + (i << 5)];
        s = fmaf(v.x, v.x, s); s = fmaf(v.y, v.y, s);
        s = fmaf(v.z, v.z, s); s = fmaf(v.w, v.w, s);
    }
#pragma unroll
    for (int o = 16; o; o >>= 1) s += __shfl_xor_sync(0xffffffffu, s, o);
    if (lane == 0) g_csq[row] = s;
}

// ---------------- GEMM (NT, row-major A[T,512] * B[512,512]^T + bias) ------
__global__ __launch_bounds__(256) void gemm_nt_bias(
    const float* __restrict__ A, const float* __restrict__ B,
    const float* __restrict__ bias, float* __restrict__ Out)
{
    __shared__ float As[32 * 64];
    __shared__ float Bs[32 * 64];
    const int m0 = blockIdx.x * 64;
    const int n0 = blockIdx.y * 64;
    const int tid = threadIdx.x;
    const int tx = tid & 15, ty = tid >> 4;

    float acc[4][4] = {};
    for (int k0 = 0; k0 < DDIM; k0 += 32) {
#pragma unroll
        for (int l = 0; l < 2; l++) {
            int f  = tid + (l << 8);
            int r  = f >> 3;
            int c4 = (f & 7) << 2;
            float4 va = *(const float4*)(A + (size_t)(m0 + r) * DDIM + k0 + c4);
            As[SW(c4 + 0, r)] = va.x; As[SW(c4 + 1, r)] = va.y;
            As[SW(c4 + 2, r)] = va.z; As[SW(c4 + 3, r)] = va.w;
            float4 vb = *(const float4*)(B + (size_t)(n0 + r) * DDIM + k0 + c4);
            Bs[SW(c4 + 0, r)] = vb.x; Bs[SW(c4 + 1, r)] = vb.y;
            Bs[SW(c4 + 2, r)] = vb.z; Bs[SW(c4 + 3, r)] = vb.w;
        }
        __syncthreads();
#pragma unroll 8
        for (int k = 0; k < 32; k++) {
            float4 av = *(const float4*)(As + SW(k, ty << 2));
            float4 bv = *(const float4*)(Bs + SW(k, tx << 2));
            float a[4] = {av.x, av.y, av.z, av.w};
            float b[4] = {bv.x, bv.y, bv.z, bv.w};
#pragma unroll
            for (int i = 0; i < 4; i++)
#pragma unroll
                for (int j = 0; j < 4; j++)
                    acc[i][j] = fmaf(a[i], b[j], acc[i][j]);
        }
        __syncthreads();
    }
    float4 bb = *(const float4*)(bias + n0 + (tx << 2));
    float bj[4] = {bb.x, bb.y, bb.z, bb.w};
#pragma unroll
    for (int i = 0; i < 4; i++) {
        float4 o;
        o.x = acc[i][0] + bj[0];
        o.y = acc[i][1] + bj[1];
        o.z = acc[i][2] + bj[2];
        o.w = acc[i][3] + bj[3];
        *(float4*)(Out + (size_t)(m0 + (ty << 2) + i) * DDIM + n0 + (tx << 2)) = o;
    }
}

// ---------------- fused distance-GEMM + row argmin over all K --------------
// dist[t,k] = ||c_k||^2 - 2 * (r_t . c_k); emits argmin_k into g_idx.
__global__ __launch_bounds__(256) void vq_argmin(
    const float* __restrict__ Rm, const float* __restrict__ C)
{
    __shared__ float As[32 * 64];
    __shared__ float Bs[32 * 64];
    __shared__ unsigned long long red[64];

    const int m0 = blockIdx.x * 64;
    const int tid = threadIdx.x;
    const int tx = tid & 15, ty = tid >> 4;

    float    bestv[4];
    unsigned besti[4];
#pragma unroll
    for (int i = 0; i < 4; i++) { bestv[i] = __int_as_float(0x7f800000); besti[i] = 0u; }

    for (int n0 = 0; n0 < KCB; n0 += 64) {
        float acc[4][4] = {};
        for (int k0 = 0; k0 < DDIM; k0 += 32) {
#pragma unroll
            for (int l = 0; l < 2; l++) {
                int f  = tid + (l << 8);
                int r  = f >> 3;
                int c4 = (f & 7) << 2;
                float4 va = *(const float4*)(Rm + (size_t)(m0 + r) * DDIM + k0 + c4);
                As[SW(c4 + 0, r)] = va.x; As[SW(c4 + 1, r)] = va.y;
                As[SW(c4 + 2, r)] = va.z; As[SW(c4 + 3, r)] = va.w;
                float4 vb = *(const float4*)(C + (size_t)(n0 + r) * DDIM + k0 + c4);
                Bs[SW(c4 + 0, r)] = vb.x; Bs[SW(c4 + 1, r)] = vb.y;
                Bs[SW(c4 + 2, r)] = vb.z; Bs[SW(c4 + 3, r)] = vb.w;
            }
            __syncthreads();
#pragma unroll 8
            for (int k = 0; k < 32; k++) {
                float4 av = *(const float4*)(As + SW(k, ty << 2));
                float4 bv = *(const float4*)(Bs + SW(k, tx << 2));
                float a[4] = {av.x, av.y, av.z, av.w};
                float b[4] = {bv.x, bv.y, bv.z, bv.w};
#pragma unroll
                for (int i = 0; i < 4; i++)
#pragma unroll
                    for (int j = 0; j < 4; j++)
                        acc[i][j] = fmaf(a[i], b[j], acc[i][j]);
            }
            __syncthreads();
        }
        float cs[4];
        *(float4*)cs = *(const float4*)(g_csq + n0 + (tx << 2));
#pragma unroll
        for (int j = 0; j < 4; j++) {
#pragma unroll
            for (int i = 0; i < 4; i++) {
                float d = fmaf(-2.0f, acc[i][j], cs[j]);
                if (d < bestv[i]) {                 // strict < keeps first (lowest idx)
                    bestv[i] = d;
                    besti[i] = (unsigned)(n0 + (tx << 2) + j);
                }
            }
        }
    }

    if (tid < 64) red[tid] = ~0ULL;
    __syncthreads();
#pragma unroll
    for (int i = 0; i < 4; i++) {
        unsigned long long key =
            ((unsigned long long)fkey(bestv[i]) << 32) | (unsigned long long)besti[i];
        atomicMin(&red[(ty << 2) + i], key);        // ties -> lowest idx (matches jnp.argmin)
    }
    __syncthreads();
    if (tid < 64) g_idx[m0 + tid] = (int)(red[tid] & 0xffffffffu);
}

// ---------------- gather + accumulate + residual update --------------------
__global__ void vq_apply(const float* __restrict__ C, int stage) {
    int t  = blockIdx.x;
    int id = g_idx[t];
    const float4* c = (const float4*)(C + (size_t)id * DDIM);
    float4* q = (float4*)(g_qsum + (size_t)t * DDIM);
    float4* r = (float4*)(g_res  + (size_t)t * DDIM);
    int i = threadIdx.x;                            // 128 threads x float4 = 512
    float4 cv = c[i];
    if (stage == 0) {
        q[i] = cv;
        float4 rv = r[i];
        rv.x -= cv.x; rv.y -= cv.y; rv.z -= cv.z; rv.w -= cv.w;
        r[i] = rv;
    } else {                                        // last stage: residual not needed
        float4 qv = q[i];
        qv.x += cv.x; qv.y += cv.y; qv.z += cv.z; qv.w += cv.w;
        q[i] = qv;
    }
}

// ---------------- launch ----------------------------------------------------
extern "C" void kernel_launch(void* const* d_in, const int* in_sizes, int n_in,
                              void* d_out, int out_size)
{
    const float* x     = (const float*)d_in[0];
    const float* enc_w = (const float*)d_in[1];
    const float* enc_b = (const float*)d_in[2];
    const float* cb    = (const float*)d_in[3];
    const float* dec_w = (const float*)d_in[4];
    const float* dec_b = (const float*)d_in[5];
    float* out = (float*)d_out;

    float *res_p, *q_p;
    cudaGetSymbolAddress((void**)&res_p, g_res);
    cudaGetSymbolAddress((void**)&q_p,   g_qsum);

    csq_kernel<<<KCB / 8, 256>>>(cb);
    gemm_nt_bias<<<dim3(TTOK / 64, DDIM / 64), 256>>>(x, enc_w, enc_b, res_p);
    vq_argmin<<<TTOK / 64, 256>>>(res_p, cb);
    vq_apply<<<TTOK, 128>>>(cb, 0);
    vq_argmin<<<TTOK / 64, 256>>>(res_p, cb);
    vq_apply<<<TTOK, 128>>>(cb, 1);
    gemm_nt_bias<<<dim3(TTOK / 64, DDIM / 64), 256>>>(q_p, dec_w, dec_b, out);
}

// round 6
// speedup vs baseline: 6.9077x; 6.9077x over previous
#include <cuda_runtime.h>
#include <cuda_bf16.h>
#include <cstdint>

#define TTOK 16384
#define DDIM 512
#define KCB  16384

// ---------------- scratch (device globals: no allocation allowed) ----------
__device__ float g_res [TTOK * DDIM];
__device__ float g_qsum[TTOK * DDIM];
__device__ float g_csq [KCB];
__device__ int   g_idx [TTOK];
__device__ __nv_bfloat16 g_res_bf[TTOK * DDIM];
__device__ __nv_bfloat16 g_cb_bf [KCB * DDIM];
__device__ int g_cand[4][TTOK];

// ---------------- helpers ---------------------------------------------------
__device__ __forceinline__ unsigned fkey(float f) {
    unsigned u = __float_as_uint(f);
    return (u & 0x80000000u) ? ~u : (u | 0x80000000u);
}
__device__ __forceinline__ uint32_t swz(uint32_t off) {      // SW128 (Swizzle<3,4,3>)
    return off ^ (((off >> 7) & 7u) << 4);
}
__device__ __forceinline__ uint32_t smem_u32(const void* p) {
    uint32_t a;
    asm("{ .reg .u64 t; cvta.to.shared.u64 t, %1; cvt.u32.u64 %0, t; }"
        : "=r"(a) : "l"(p));
    return a;
}
__device__ __forceinline__ void cp16(uint32_t dst, const void* src) {
    asm volatile("cp.async.cg.shared.global [%0], [%1], 16;" :: "r"(dst), "l"(src));
}
#define CP_COMMIT()  asm volatile("cp.async.commit_group;" ::: "memory")
#define CP_WAIT(N)   asm volatile("cp.async.wait_group %0;" :: "n"(N) : "memory")

__device__ __forceinline__ void ldsm_x4(uint32_t& r0, uint32_t& r1,
                                        uint32_t& r2, uint32_t& r3, uint32_t a) {
    asm volatile("ldmatrix.sync.aligned.m8n8.x4.shared.b16 {%0,%1,%2,%3}, [%4];"
                 : "=r"(r0), "=r"(r1), "=r"(r2), "=r"(r3) : "r"(a));
}
__device__ __forceinline__ void ldsm_x2(uint32_t& r0, uint32_t& r1, uint32_t a) {
    asm volatile("ldmatrix.sync.aligned.m8n8.x2.shared.b16 {%0,%1}, [%2];"
                 : "=r"(r0), "=r"(r1) : "r"(a));
}
__device__ __forceinline__ void mma16816(float* c, const uint32_t* a,
                                         uint32_t b0, uint32_t b1) {
    asm volatile(
        "mma.sync.aligned.m16n8k16.row.col.f32.bf16.bf16.f32 "
        "{%0,%1,%2,%3}, {%4,%5,%6,%7}, {%8,%9}, {%0,%1,%2,%3};"
        : "+f"(c[0]), "+f"(c[1]), "+f"(c[2]), "+f"(c[3])
        : "r"(a[0]), "r"(a[1]), "r"(a[2]), "r"(a[3]), "r"(b0), "r"(b1));
}
__device__ __forceinline__ void ins3(unsigned long long* t, unsigned long long k) {
    if (k < t[2]) {
        if (k < t[1]) {
            t[2] = t[1];
            if (k < t[0]) { t[1] = t[0]; t[0] = k; } else t[1] = k;
        } else t[2] = k;
    }
}
__device__ __forceinline__ unsigned long long pk(float d, int idx) {
    return ((unsigned long long)fkey(d) << 32) | (unsigned)idx;
}

// ---------------- ||c||^2 ---------------------------------------------------
__global__ void csq_kernel(const float* __restrict__ C) {
    int row  = blockIdx.x * 8 + (threadIdx.x >> 5);
    int lane = threadIdx.x & 31;
    const float4* p = (const float4*)(C + (size_t)row * DDIM);
    float s = 0.f;
#pragma unroll
    for (int i = 0; i < 4; i++) {
        float4 v = p[lane + (i << 5)];
        s = fmaf(v.x, v.x, s); s = fmaf(v.y, v.y, s);
        s = fmaf(v.z, v.z, s); s = fmaf(v.w, v.w, s);
    }
#pragma unroll
    for (int o = 16; o; o >>= 1) s += __shfl_xor_sync(0xffffffffu, s, o);
    if (lane == 0) g_csq[row] = s;
}

// ---------------- fp32 -> bf16 (codebook only) -------------------------------
__global__ void tobf16_kernel(const float* __restrict__ X,
                              __nv_bfloat16* __restrict__ Out) {
    int i = blockIdx.x * blockDim.x + threadIdx.x;   // one float4 per thread
    float4 v = ((const float4*)X)[i];
    __nv_bfloat16 h[4];
    h[0] = __float2bfloat16(v.x); h[1] = __float2bfloat16(v.y);
    h[2] = __float2bfloat16(v.z); h[3] = __float2bfloat16(v.w);
    ((uint2*)Out)[i] = *(uint2*)h;
}

// ---------------- fp32 SIMT GEMM (NT) + bias (enc/dec) ----------------------
// Optional Obf: bf16 shadow copy of the output (used for encoder -> residual).
#define SW(k, c) (((k) << 6) + ((c) ^ ((((k) >> 2) & 7) << 2)))

__global__ __launch_bounds__(256) void gemm_nt_bias(
    const float* __restrict__ A, const float* __restrict__ B,
    const float* __restrict__ bias, float* __restrict__ Out,
    __nv_bfloat16* __restrict__ Obf)
{
    __shared__ float As[32 * 64];
    __shared__ float Bs[32 * 64];
    const int m0 = blockIdx.x * 64;
    const int n0 = blockIdx.y * 64;
    const int tid = threadIdx.x;
    const int tx = tid & 15, ty = tid >> 4;

    float acc[4][4] = {};
    for (int k0 = 0; k0 < DDIM; k0 += 32) {
#pragma unroll
        for (int l = 0; l < 2; l++) {
            int f  = tid + (l << 8);
            int r  = f >> 3;
            int c4 = (f & 7) << 2;
            float4 va = *(const float4*)(A + (size_t)(m0 + r) * DDIM + k0 + c4);
            As[SW(c4 + 0, r)] = va.x; As[SW(c4 + 1, r)] = va.y;
            As[SW(c4 + 2, r)] = va.z; As[SW(c4 + 3, r)] = va.w;
            float4 vb = *(const float4*)(B + (size_t)(n0 + r) * DDIM + k0 + c4);
            Bs[SW(c4 + 0, r)] = vb.x; Bs[SW(c4 + 1, r)] = vb.y;
            Bs[SW(c4 + 2, r)] = vb.z; Bs[SW(c4 + 3, r)] = vb.w;
        }
        __syncthreads();
#pragma unroll 8
        for (int k = 0; k < 32; k++) {
            float4 av = *(const float4*)(As + SW(k, ty << 2));
            float4 bv = *(const float4*)(Bs + SW(k, tx << 2));
            float a[4] = {av.x, av.y, av.z, av.w};
            float b[4] = {bv.x, bv.y, bv.z, bv.w};
#pragma unroll
            for (int i = 0; i < 4; i++)
#pragma unroll
                for (int j = 0; j < 4; j++)
                    acc[i][j] = fmaf(a[i], b[j], acc[i][j]);
        }
        __syncthreads();
    }
    float4 bb = *(const float4*)(bias + n0 + (tx << 2));
    float bj[4] = {bb.x, bb.y, bb.z, bb.w};
#pragma unroll
    for (int i = 0; i < 4; i++) {
        float4 o;
        o.x = acc[i][0] + bj[0];
        o.y = acc[i][1] + bj[1];
        o.z = acc[i][2] + bj[2];
        o.w = acc[i][3] + bj[3];
        size_t pos = (size_t)(m0 + (ty << 2) + i) * DDIM + n0 + (tx << 2);
        *(float4*)(Out + pos) = o;
        if (Obf) {
            __nv_bfloat16 h[4];
            h[0] = __float2bfloat16(o.x); h[1] = __float2bfloat16(o.y);
            h[2] = __float2bfloat16(o.z); h[3] = __float2bfloat16(o.w);
            *(uint2*)(Obf + pos) = *(uint2*)h;
        }
    }
}

// ---------------- bf16 mma.sync distance GEMM + per-token top candidates -----
// CTA: 128 tokens, A resident in SMEM (8 chunk tiles of [128][64] bf16, SW128).
// Loops 128 N-tiles of 128 codes; B double-buffered via cp.async.
// 8 warps = 2(M) x 4(N); warp tile 64x32; mma m16n8k16 bf16->f32.
#define VQ_SMEM (131072 + 2 * 16384)

__global__ __launch_bounds__(256) void vq_topk() {
    extern __shared__ __align__(1024) char smem[];
    const int tid  = threadIdx.x;
    const int lane = tid & 31;
    const int wid  = tid >> 5;
    const int wm   = wid >> 2;        // 0..1
    const int wn   = wid & 3;         // 0..3
    const int m0   = blockIdx.x * 128;
    const uint32_t sA = smem_u32(smem);
    const uint32_t sB = sA + 131072;

    // preload resident A (128 x 512 bf16 = 128 KB)
#pragma unroll 4
    for (int u = tid; u < 8192; u += 256) {
        int chunk = u >> 10, rem = u & 1023;
        int r = rem >> 3, c16 = rem & 7;
        cp16(sA + chunk * 16384 + swz((uint32_t)(r * 128 + c16 * 16)),
             g_res_bf + (size_t)(m0 + r) * DDIM + chunk * 64 + c16 * 8);
    }
    CP_COMMIT();
    // first B chunk (n-tile 0, k-chunk 0)
#pragma unroll
    for (int j = 0; j < 4; j++) {
        int u = tid + j * 256;
        int r = u >> 3, c16 = u & 7;
        cp16(sB + swz((uint32_t)(r * 128 + c16 * 16)),
             g_cb_bf + (size_t)r * DDIM + c16 * 8);
    }
    CP_COMMIT();

    unsigned long long top[8][3];
#pragma unroll
    for (int i = 0; i < 8; i++)
#pragma unroll
        for (int j = 0; j < 3; j++) top[i][j] = ~0ULL;

    float acc[4][4][4];
#pragma unroll
    for (int a = 0; a < 4; a++)
#pragma unroll
        for (int b = 0; b < 4; b++)
#pragma unroll
            for (int c = 0; c < 4; c++) acc[a][b][c] = 0.f;

    const int lb = lane & 15;

    for (int it = 0; it < 1024; ++it) {                 // 128 n-tiles x 8 k-chunks
        if (it + 1 < 1024) {
            const int nx  = it + 1;
            const int nn0 = (nx >> 3) << 7;
            const int nch = nx & 7;
            const uint32_t bb = sB + (uint32_t)(nx & 1) * 16384;
#pragma unroll
            for (int j = 0; j < 4; j++) {
                int u = tid + j * 256;
                int r = u >> 3, c16 = u & 7;
                cp16(bb + swz((uint32_t)(r * 128 + c16 * 16)),
                     g_cb_bf + (size_t)(nn0 + r) * DDIM + nch * 64 + c16 * 8);
            }
            CP_COMMIT();
            CP_WAIT(1);
        } else {
            CP_WAIT(0);
        }
        __syncthreads();

        const int ch = it & 7;
        const uint32_t abase = sA + (uint32_t)ch * 16384;
        const uint32_t bbase = sB + (uint32_t)(it & 1) * 16384;
#pragma unroll
        for (int kk = 0; kk < 4; kk++) {
            uint32_t afr[4][4];
#pragma unroll
            for (int im = 0; im < 4; im++) {
                uint32_t off = (uint32_t)((wm * 64 + im * 16 + (lane & 15)) * 128
                                          + kk * 32 + (lane >> 4) * 16);
                ldsm_x4(afr[im][0], afr[im][1], afr[im][2], afr[im][3],
                        abase + swz(off));
            }
#pragma unroll
            for (int in = 0; in < 4; in++) {
                uint32_t off = (uint32_t)((wn * 32 + in * 8 + (lb & 7)) * 128
                                          + kk * 32 + ((lb >> 3) & 1) * 16);
                uint32_t b0, b1;
                ldsm_x2(b0, b1, bbase + swz(off));
#pragma unroll
                for (int im = 0; im < 4; im++)
                    mma16816(acc[im][in], afr[im], b0, b1);
            }
        }

        if (ch == 7) {                                  // fold N-tile into top-3
            const int n0 = (it >> 3) << 7;
#pragma unroll
            for (int in = 0; in < 4; in++) {
                const int ncol = n0 + wn * 32 + in * 8 + (lane & 3) * 2;
                const float cs0 = __ldg(g_csq + ncol);
                const float cs1 = __ldg(g_csq + ncol + 1);
#pragma unroll
                for (int im = 0; im < 4; im++) {
                    float d;
                    d = fmaf(-2.f, acc[im][in][0], cs0); ins3(top[im * 2],     pk(d, ncol));
                    d = fmaf(-2.f, acc[im][in][1], cs1); ins3(top[im * 2],     pk(d, ncol + 1));
                    d = fmaf(-2.f, acc[im][in][2], cs0); ins3(top[im * 2 + 1], pk(d, ncol));
                    d = fmaf(-2.f, acc[im][in][3], cs1); ins3(top[im * 2 + 1], pk(d, ncol + 1));
                    acc[im][in][0] = 0.f; acc[im][in][1] = 0.f;
                    acc[im][in][2] = 0.f; acc[im][in][3] = 0.f;
                }
            }
        }
        __syncthreads();
    }

    // merge per-lane top-3 lists (16 lanes per token) via smem (reuse A region)
    unsigned long long* cand = (unsigned long long*)smem;
#pragma unroll
    for (int im = 0; im < 4; im++)
#pragma unroll
        for (int h = 0; h < 2; h++) {
            int token = wm * 64 + im * 16 + h * 8 + (lane >> 2);
            int slot  = wn * 4 + (lane & 3);
            size_t base = ((size_t)token * 16 + slot) * 3;
            cand[base + 0] = top[im * 2 + h][0];
            cand[base + 1] = top[im * 2 + h][1];
            cand[base + 2] = top[im * 2 + h][2];
        }
    __syncthreads();
    if (tid < 128) {
        unsigned long long b0 = ~0ULL, b1 = ~0ULL, b2 = ~0ULL, b3 = ~0ULL;
        const unsigned long long* p = cand + (size_t)tid * 48;
        for (int i = 0; i < 48; i++) {
            unsigned long long k = p[i];
            if (k < b3) {
                if (k < b2) {
                    b3 = b2;
                    if (k < b1) {
                        b2 = b1;
                        if (k < b0) { b1 = b0; b0 = k; } else b1 = k;
                    } else b2 = k;
                } else b3 = k;
            }
        }
        const int t = m0 + tid;
        g_cand[0][t] = (int)(b0 & 0xffffffffu);
        g_cand[1][t] = (int)(b1 & 0xffffffffu);
        g_cand[2][t] = (int)(b2 & 0xffffffffu);
        g_cand[3][t] = (int)(b3 & 0xffffffffu);
    }
}

// ---------------- exact fp32 refine over 4 candidates ------------------------
__global__ void refine_kernel(const float* __restrict__ C) {
    const int wid  = threadIdx.x >> 5;
    const int lane = threadIdx.x & 31;
    const int t = blockIdx.x * 8 + wid;
    int cd[4];
#pragma unroll
    for (int j = 0; j < 4; j++) cd[j] = g_cand[j][t];
    const float4* r4 = (const float4*)(g_res + (size_t)t * DDIM);
    float s[4] = {0.f, 0.f, 0.f, 0.f};
#pragma unroll
    for (int i = 0; i < 4; i++) {
        float4 rv = r4[lane + i * 32];
#pragma unroll
        for (int j = 0; j < 4; j++) {
            float4 cv = __ldg((const float4*)(C + (size_t)cd[j] * DDIM) + lane + i * 32);
            s[j] = fmaf(rv.x, cv.x, s[j]); s[j] = fmaf(rv.y, cv.y, s[j]);
            s[j] = fmaf(rv.z, cv.z, s[j]); s[j] = fmaf(rv.w, cv.w, s[j]);
        }
    }
#pragma unroll
    for (int j = 0; j < 4; j++)
#pragma unroll
        for (int o = 16; o; o >>= 1) s[j] += __shfl_xor_sync(0xffffffffu, s[j], o);
    if (lane == 0) {
        float bd = __int_as_float(0x7f800000);
        int   bi = 0x7fffffff;
#pragma unroll
        for (int j = 0; j < 4; j++) {
            float d = fmaf(-2.f, s[j], g_csq[cd[j]]);
            if (d < bd || (d == bd && cd[j] < bi)) { bd = d; bi = cd[j]; }
        }
        g_idx[t] = bi;
    }
}

// ---------------- gather + accumulate + residual update ---------------------
__global__ void vq_apply(const float* __restrict__ C, int stage) {
    int t  = blockIdx.x;
    int id = g_idx[t];
    const float4* c = (const float4*)(C + (size_t)id * DDIM);
    float4* q = (float4*)(g_qsum + (size_t)t * DDIM);
    float4* r = (float4*)(g_res  + (size_t)t * DDIM);
    int i = threadIdx.x;
    float4 cv = c[i];
    if (stage == 0) {
        q[i] = cv;
        float4 rv = r[i];
        rv.x -= cv.x; rv.y -= cv.y; rv.z -= cv.z; rv.w -= cv.w;
        r[i] = rv;
        __nv_bfloat16 h[4];                         // bf16 shadow for stage-1 GEMM
        h[0] = __float2bfloat16(rv.x); h[1] = __float2bfloat16(rv.y);
        h[2] = __float2bfloat16(rv.z); h[3] = __float2bfloat16(rv.w);
        *((uint2*)(g_res_bf + (size_t)t * DDIM) + i) = *(uint2*)h;
    } else {
        float4 qv = q[i];
        qv.x += cv.x; qv.y += cv.y; qv.z += cv.z; qv.w += cv.w;
        q[i] = qv;
    }
}

// ---------------- launch ----------------------------------------------------
extern "C" void kernel_launch(void* const* d_in, const int* in_sizes, int n_in,
                              void* d_out, int out_size)
{
    const float* x     = (const float*)d_in[0];
    const float* enc_w = (const float*)d_in[1];
    const float* enc_b = (const float*)d_in[2];
    const float* cb    = (const float*)d_in[3];
    const float* dec_w = (const float*)d_in[4];
    const float* dec_b = (const float*)d_in[5];
    float* out = (float*)d_out;

    float *res_p, *q_p;
    __nv_bfloat16 *rb_p, *cbb_p;
    cudaGetSymbolAddress((void**)&res_p, g_res);
    cudaGetSymbolAddress((void**)&q_p,   g_qsum);
    cudaGetSymbolAddress((void**)&rb_p,  g_res_bf);
    cudaGetSymbolAddress((void**)&cbb_p, g_cb_bf);

    cudaFuncSetAttribute(vq_topk, cudaFuncAttributeMaxDynamicSharedMemorySize, VQ_SMEM);

    csq_kernel<<<KCB / 8, 256>>>(cb);
    tobf16_kernel<<<(KCB * DDIM / 4) / 256, 256>>>(cb, cbb_p);
    // encoder GEMM also emits bf16 residual shadow
    gemm_nt_bias<<<dim3(TTOK / 64, DDIM / 64), 256>>>(x, enc_w, enc_b, res_p, rb_p);

    // stage 0
    vq_topk<<<TTOK / 128, 256, VQ_SMEM>>>();
    refine_kernel<<<TTOK / 8, 256>>>(cb);
    vq_apply<<<TTOK, 128>>>(cb, 0);   // updates g_res and g_res_bf

    // stage 1
    vq_topk<<<TTOK / 128, 256, VQ_SMEM>>>();
    refine_kernel<<<TTOK / 8, 256>>>(cb);
    vq_apply<<<TTOK, 128>>>(cb, 1);

    gemm_nt_bias<<<dim3(TTOK / 64, DDIM / 64), 256>>>(q_p, dec_w, dec_b, out, nullptr);
}

// round 11
// speedup vs baseline: 7.9350x; 1.1487x over previous
#include <cuda_runtime.h>
#include <cuda_bf16.h>
#include <cstdint>

#define TTOK 16384
#define DDIM 512
#define KCB  16384

// ---------------- scratch (device globals: no allocation allowed) ----------
__device__ float g_res [TTOK * DDIM];
__device__ float g_qsum[TTOK * DDIM];
__device__ float g_csq [KCB];
__device__ int   g_idx [TTOK];
__device__ __nv_bfloat16 g_res_bf[TTOK * DDIM];
__device__ __nv_bfloat16 g_cb_bf [KCB * DDIM];
__device__ __nv_bfloat16 g_a_hi[TTOK * DDIM];   // activation hi/lo for enc/dec GEMM
__device__ __nv_bfloat16 g_a_lo[TTOK * DDIM];
__device__ __nv_bfloat16 g_w_hi[DDIM * DDIM];   // weight hi/lo
__device__ __nv_bfloat16 g_w_lo[DDIM * DDIM];
__device__ int g_cand[4][TTOK];

// ---------------- helpers ---------------------------------------------------
__device__ __forceinline__ unsigned fkey(float f) {
    unsigned u = __float_as_uint(f);
    return (u & 0x80000000u) ? ~u : (u | 0x80000000u);
}
__device__ __forceinline__ uint32_t swz(uint32_t off) {      // SW128 (Swizzle<3,4,3>)
    return off ^ (((off >> 7) & 7u) << 4);
}
__device__ __forceinline__ uint32_t smem_u32(const void* p) {
    uint32_t a;
    asm("{ .reg .u64 t; cvta.to.shared.u64 t, %1; cvt.u32.u64 %0, t; }"
        : "=r"(a) : "l"(p));
    return a;
}
__device__ __forceinline__ void cp16(uint32_t dst, const void* src) {
    asm volatile("cp.async.cg.shared.global [%0], [%1], 16;" :: "r"(dst), "l"(src));
}
#define CP_COMMIT()  asm volatile("cp.async.commit_group;" ::: "memory")
#define CP_WAIT(N)   asm volatile("cp.async.wait_group %0;" :: "n"(N) : "memory")

__device__ __forceinline__ void ldsm_x4(uint32_t& r0, uint32_t& r1,
                                        uint32_t& r2, uint32_t& r3, uint32_t a) {
    asm volatile("ldmatrix.sync.aligned.m8n8.x4.shared.b16 {%0,%1,%2,%3}, [%4];"
                 : "=r"(r0), "=r"(r1), "=r"(r2), "=r"(r3) : "r"(a));
}
__device__ __forceinline__ void ldsm_x2(uint32_t& r0, uint32_t& r1, uint32_t a) {
    asm volatile("ldmatrix.sync.aligned.m8n8.x2.shared.b16 {%0,%1}, [%2];"
                 : "=r"(r0), "=r"(r1) : "r"(a));
}
__device__ __forceinline__ void mma16816(float* c, const uint32_t* a,
                                         uint32_t b0, uint32_t b1) {
    asm volatile(
        "mma.sync.aligned.m16n8k16.row.col.f32.bf16.bf16.f32 "
        "{%0,%1,%2,%3}, {%4,%5,%6,%7}, {%8,%9}, {%0,%1,%2,%3};"
        : "+f"(c[0]), "+f"(c[1]), "+f"(c[2]), "+f"(c[3])
        : "r"(a[0]), "r"(a[1]), "r"(a[2]), "r"(a[3]), "r"(b0), "r"(b1));
}
__device__ __forceinline__ void ins3(unsigned long long* t, unsigned long long k) {
    if (k < t[2]) {
        if (k < t[1]) {
            t[2] = t[1];
            if (k < t[0]) { t[1] = t[0]; t[0] = k; } else t[1] = k;
        } else t[2] = k;
    }
}
__device__ __forceinline__ unsigned long long pk(float d, int idx) {
    return ((unsigned long long)fkey(d) << 32) | (unsigned)idx;
}

// ---------------- ||c||^2 ---------------------------------------------------
__global__ void csq_kernel(const float* __restrict__ C) {
    int row  = blockIdx.x * 8 + (threadIdx.x >> 5);
    int lane = threadIdx.x & 31;
    const float4* p = (const float4*)(C + (size_t)row * DDIM);
    float s = 0.f;
#pragma unroll
    for (int i = 0; i < 4; i++) {
        float4 v = p[lane + (i << 5)];
        s = fmaf(v.x, v.x, s); s = fmaf(v.y, v.y, s);
        s = fmaf(v.z, v.z, s); s = fmaf(v.w, v.w, s);
    }
#pragma unroll
    for (int o = 16; o; o >>= 1) s += __shfl_xor_sync(0xffffffffu, s, o);
    if (lane == 0) g_csq[row] = s;
}

// ---------------- fp32 -> bf16 (single) -------------------------------------
__global__ void tobf16_kernel(const float* __restrict__ X,
                              __nv_bfloat16* __restrict__ Out) {
    int i = blockIdx.x * blockDim.x + threadIdx.x;
    float4 v = ((const float4*)X)[i];
    __nv_bfloat16 h[4];
    h[0] = __float2bfloat16(v.x); h[1] = __float2bfloat16(v.y);
    h[2] = __float2bfloat16(v.z); h[3] = __float2bfloat16(v.w);
    ((uint2*)Out)[i] = *(uint2*)h;
}

// ---------------- fp32 -> bf16 hi/lo split ----------------------------------
__global__ void splithl_kernel(const float* __restrict__ X,
                               __nv_bfloat16* __restrict__ Hi,
                               __nv_bfloat16* __restrict__ Lo) {
    int i = blockIdx.x * blockDim.x + threadIdx.x;
    float4 v = ((const float4*)X)[i];
    float f[4] = {v.x, v.y, v.z, v.w};
    __nv_bfloat16 h[4], l[4];
#pragma unroll
    for (int j = 0; j < 4; j++) {
        h[j] = __float2bfloat16(f[j]);
        l[j] = __float2bfloat16(f[j] - __bfloat162float(h[j]));
    }
    ((uint2*)Hi)[i] = *(uint2*)h;
    ((uint2*)Lo)[i] = *(uint2*)l;
}

// ---------------- bf16x3 HMMA GEMM (NT) + bias: C = A*B^T + b ----------------
// A,B given as hi/lo bf16 pairs; accumulates Ah*Bh + Ah*Bl + Al*Bh in fp32.
// CTA tile 128x128, 8 warps (2x4), warp tile 64x32. K=512 in 8 chunks of 64.
#define G3_SMEM 65536

__global__ __launch_bounds__(256) void gemm3_nt_bias(
    const __nv_bfloat16* __restrict__ Ah, const __nv_bfloat16* __restrict__ Al,
    const __nv_bfloat16* __restrict__ Bh, const __nv_bfloat16* __restrict__ Bl,
    const float* __restrict__ bias, float* __restrict__ Out,
    __nv_bfloat16* __restrict__ Obf)
{
    extern __shared__ __align__(1024) char smem[];
    const int tid  = threadIdx.x;
    const int lane = tid & 31;
    const int wid  = tid >> 5;
    const int wm   = wid >> 2;
    const int wn   = wid & 3;
    const int m0   = blockIdx.x * 128;
    const int n0   = blockIdx.y * 128;
    const uint32_t sAh = smem_u32(smem);
    const uint32_t sAl = sAh + 16384;
    const uint32_t sBh = sAh + 32768;
    const uint32_t sBl = sAh + 49152;
    const int lb = lane & 15;

    float acc[4][4][4];
#pragma unroll
    for (int a = 0; a < 4; a++)
#pragma unroll
        for (int b = 0; b < 4; b++)
#pragma unroll
            for (int c = 0; c < 4; c++) acc[a][b][c] = 0.f;

    for (int ch = 0; ch < 8; ++ch) {
        const int k0 = ch << 6;
#pragma unroll
        for (int j = 0; j < 4; j++) {
            int u = tid + j * 256;
            int r = u >> 3, c16 = u & 7;
            uint32_t so = swz((uint32_t)(r * 128 + c16 * 16));
            size_t ga = (size_t)(m0 + r) * DDIM + k0 + c16 * 8;
            size_t gb = (size_t)(n0 + r) * DDIM + k0 + c16 * 8;
            cp16(sAh + so, Ah + ga);
            cp16(sAl + so, Al + ga);
            cp16(sBh + so, Bh + gb);
            cp16(sBl + so, Bl + gb);
        }
        CP_COMMIT();
        CP_WAIT(0);
        __syncthreads();

#pragma unroll
        for (int p = 0; p < 3; p++) {
            const uint32_t abase = (p == 2) ? sAl : sAh;
            const uint32_t bbase = (p == 1) ? sBl : sBh;
#pragma unroll
            for (int kk = 0; kk < 4; kk++) {
                uint32_t afr[4][4];
#pragma unroll
                for (int im = 0; im < 4; im++) {
                    uint32_t off = (uint32_t)((wm * 64 + im * 16 + (lane & 15)) * 128
                                              + kk * 32 + (lane >> 4) * 16);
                    ldsm_x4(afr[im][0], afr[im][1], afr[im][2], afr[im][3],
                            abase + swz(off));
                }
#pragma unroll
                for (int in = 0; in < 4; in++) {
                    uint32_t off = (uint32_t)((wn * 32 + in * 8 + (lb & 7)) * 128
                                              + kk * 32 + ((lb >> 3) & 1) * 16);
                    uint32_t b0, b1;
                    ldsm_x2(b0, b1, bbase + swz(off));
#pragma unroll
                    for (int im = 0; im < 4; im++)
                        mma16816(acc[im][in], afr[im], b0, b1);
                }
            }
        }
        __syncthreads();
    }

    // epilogue: bias + store fp32 (+ optional bf16 shadow)
#pragma unroll
    for (int in = 0; in < 4; in++) {
        const int col = n0 + wn * 32 + in * 8 + (lane & 3) * 2;
        const float b0 = __ldg(bias + col);
        const float b1 = __ldg(bias + col + 1);
#pragma unroll
        for (int im = 0; im < 4; im++) {
            const int r0 = m0 + wm * 64 + im * 16 + (lane >> 2);
            float2 o0 = make_float2(acc[im][in][0] + b0, acc[im][in][1] + b1);
            float2 o1 = make_float2(acc[im][in][2] + b0, acc[im][in][3] + b1);
            *(float2*)(Out + (size_t)r0 * DDIM + col)       = o0;
            *(float2*)(Out + (size_t)(r0 + 8) * DDIM + col) = o1;
            if (Obf) {
                __nv_bfloat16 h0[2] = {__float2bfloat16(o0.x), __float2bfloat16(o0.y)};
                __nv_bfloat16 h1[2] = {__float2bfloat16(o1.x), __float2bfloat16(o1.y)};
                *(uint32_t*)(Obf + (size_t)r0 * DDIM + col)       = *(uint32_t*)h0;
                *(uint32_t*)(Obf + (size_t)(r0 + 8) * DDIM + col) = *(uint32_t*)h1;
            }
        }
    }
}

// ---------------- bf16 mma.sync distance GEMM + per-token top candidates -----
// CTA: 128 tokens, A resident in SMEM (8 chunk tiles of [128][64] bf16, SW128).
// Loops 64 N-tiles of 256 codes; B (32KB/chunk) double-buffered via cp.async.
// 8 warps = 2(M) x 4(N); warp tile 64x64; mma m16n8k16 bf16->f32.
#define VQ_SMEM (131072 + 2 * 32768)

__global__ __launch_bounds__(256) void vq_topk() {
    extern __shared__ __align__(1024) char smem[];
    const int tid  = threadIdx.x;
    const int lane = tid & 31;
    const int wid  = tid >> 5;
    const int wm   = wid >> 2;        // 0..1
    const int wn   = wid & 3;         // 0..3
    const int m0   = blockIdx.x * 128;
    const uint32_t sA = smem_u32(smem);
    const uint32_t sB = sA + 131072;

    // preload resident A (128 x 512 bf16 = 128 KB)
#pragma unroll 4
    for (int u = tid; u < 8192; u += 256) {
        int chunk = u >> 10, rem = u & 1023;
        int r = rem >> 3, c16 = rem & 7;
        cp16(sA + chunk * 16384 + swz((uint32_t)(r * 128 + c16 * 16)),
             g_res_bf + (size_t)(m0 + r) * DDIM + chunk * 64 + c16 * 8);
    }
    CP_COMMIT();
    // first B chunk (n-tile 0, k-chunk 0): 256 rows x 64 cols
#pragma unroll
    for (int j = 0; j < 8; j++) {
        int u = tid + j * 256;
        int r = u >> 3, c16 = u & 7;
        cp16(sB + swz((uint32_t)(r * 128 + c16 * 16)),
             g_cb_bf + (size_t)r * DDIM + c16 * 8);
    }
    CP_COMMIT();

    unsigned long long top[8][3];
#pragma unroll
    for (int i = 0; i < 8; i++)
#pragma unroll
        for (int j = 0; j < 3; j++) top[i][j] = ~0ULL;

    float acc[4][8][4];
#pragma unroll
    for (int a = 0; a < 4; a++)
#pragma unroll
        for (int b = 0; b < 8; b++)
#pragma unroll
            for (int c = 0; c < 4; c++) acc[a][b][c] = 0.f;

    const int lb = lane & 15;

    for (int it = 0; it < 512; ++it) {                  // 64 n-tiles x 8 k-chunks
        if (it + 1 < 512) {
            const int nx  = it + 1;
            const int nn0 = (nx >> 3) << 8;
            const int nch = nx & 7;
            const uint32_t bb = sB + (uint32_t)(nx & 1) * 32768;
#pragma unroll
            for (int j = 0; j < 8; j++) {
                int u = tid + j * 256;
                int r = u >> 3, c16 = u & 7;
                cp16(bb + swz((uint32_t)(r * 128 + c16 * 16)),
                     g_cb_bf + (size_t)(nn0 + r) * DDIM + nch * 64 + c16 * 8);
            }
            CP_COMMIT();
            CP_WAIT(1);
        } else {
            CP_WAIT(0);
        }
        __syncthreads();

        const int ch = it & 7;
        const uint32_t abase = sA + (uint32_t)ch * 16384;
        const uint32_t bbase = sB + (uint32_t)(it & 1) * 32768;
#pragma unroll
        for (int kk = 0; kk < 4; kk++) {
            uint32_t afr[4][4];
#pragma unroll
            for (int im = 0; im < 4; im++) {
                uint32_t off = (uint32_t)((wm * 64 + im * 16 + (lane & 15)) * 128
                                          + kk * 32 + (lane >> 4) * 16);
                ldsm_x4(afr[im][0], afr[im][1], afr[im][2], afr[im][3],
                        abase + swz(off));
            }
#pragma unroll
            for (int in = 0; in < 8; in++) {
                uint32_t off = (uint32_t)((wn * 64 + in * 8 + (lb & 7)) * 128
                                          + kk * 32 + ((lb >> 3) & 1) * 16);
                uint32_t b0, b1;
                ldsm_x2(b0, b1, bbase + swz(off));
#pragma unroll
                for (int im = 0; im < 4; im++)
                    mma16816(acc[im][in], afr[im], b0, b1);
            }
        }

        if (ch == 7) {                                  // fold N-tile into top-3
            const int n0 = (it >> 3) << 8;
#pragma unroll
            for (int in = 0; in < 8; in++) {
                const int ncol = n0 + wn * 64 + in * 8 + (lane & 3) * 2;
                const float cs0 = __ldg(g_csq + ncol);
                const float cs1 = __ldg(g_csq + ncol + 1);
#pragma unroll
                for (int im = 0; im < 4; im++) {
                    float d;
                    d = fmaf(-2.f, acc[im][in][0], cs0); ins3(top[im * 2],     pk(d, ncol));
                    d = fmaf(-2.f, acc[im][in][1], cs1); ins3(top[im * 2],     pk(d, ncol + 1));
                    d = fmaf(-2.f, acc[im][in][2], cs0); ins3(top[im * 2 + 1], pk(d, ncol));
                    d = fmaf(-2.f, acc[im][in][3], cs1); ins3(top[im * 2 + 1], pk(d, ncol + 1));
                    acc[im][in][0] = 0.f; acc[im][in][1] = 0.f;
                    acc[im][in][2] = 0.f; acc[im][in][3] = 0.f;
                }
            }
        }
        __syncthreads();
    }

    // merge per-lane top-3 lists (16 lane-slots per token) via smem (reuse A)
    unsigned long long* cand = (unsigned long long*)smem;
#pragma unroll
    for (int im = 0; im < 4; im++)
#pragma unroll
        for (int h = 0; h < 2; h++) {
            int token = wm * 64 + im * 16 + h * 8 + (lane >> 2);
            int slot  = wn * 4 + (lane & 3);
            size_t base = ((size_t)token * 16 + slot) * 3;
            cand[base + 0] = top[im * 2 + h][0];
            cand[base + 1] = top[im * 2 + h][1];
            cand[base + 2] = top[im * 2 + h][2];
        }
    __syncthreads();
    if (tid < 128) {
        unsigned long long b0 = ~0ULL, b1 = ~0ULL, b2 = ~0ULL, b3 = ~0ULL;
        const unsigned long long* p = cand + (size_t)tid * 48;
        for (int i = 0; i < 48; i++) {
            unsigned long long k = p[i];
            if (k < b3) {
                if (k < b2) {
                    b3 = b2;
                    if (k < b1) {
                        b2 = b1;
                        if (k < b0) { b1 = b0; b0 = k; } else b1 = k;
                    } else b2 = k;
                } else b3 = k;
            }
        }
        const int t = m0 + tid;
        g_cand[0][t] = (int)(b0 & 0xffffffffu);
        g_cand[1][t] = (int)(b1 & 0xffffffffu);
        g_cand[2][t] = (int)(b2 & 0xffffffffu);
        g_cand[3][t] = (int)(b3 & 0xffffffffu);
    }
}

// ---------------- exact fp32 refine over 4 candidates ------------------------
__global__ void refine_kernel(const float* __restrict__ C) {
    const int wid  = threadIdx.x >> 5;
    const int lane = threadIdx.x & 31;
    const int t = blockIdx.x * 8 + wid;
    int cd[4];
#pragma unroll
    for (int j = 0; j < 4; j++) cd[j] = g_cand[j][t];
    const float4* r4 = (const float4*)(g_res + (size_t)t * DDIM);
    float s[4] = {0.f, 0.f, 0.f, 0.f};
#pragma unroll
    for (int i = 0; i < 4; i++) {
        float4 rv = r4[lane + i * 32];
#pragma unroll
        for (int j = 0; j < 4; j++) {
            float4 cv = __ldg((const float4*)(C + (size_t)cd[j] * DDIM) + lane + i * 32);
            s[j] = fmaf(rv.x, cv.x, s[j]); s[j] = fmaf(rv.y, cv.y, s[j]);
            s[j] = fmaf(rv.z, cv.z, s[j]); s[j] = fmaf(rv.w, cv.w, s[j]);
        }
    }
#pragma unroll
    for (int j = 0; j < 4; j++)
#pragma unroll
        for (int o = 16; o; o >>= 1) s[j] += __shfl_xor_sync(0xffffffffu, s[j], o);
    if (lane == 0) {
        float bd = __int_as_float(0x7f800000);
        int   bi = 0x7fffffff;
#pragma unroll
        for (int j = 0; j < 4; j++) {
            float d = fmaf(-2.f, s[j], g_csq[cd[j]]);
            if (d < bd || (d == bd && cd[j] < bi)) { bd = d; bi = cd[j]; }
        }
        g_idx[t] = bi;
    }
}

// ---------------- gather + accumulate + residual update ---------------------
__global__ void vq_apply(const float* __restrict__ C, int stage) {
    int t  = blockIdx.x;
    int id = g_idx[t];
    const float4* c = (const float4*)(C + (size_t)id * DDIM);
    float4* q = (float4*)(g_qsum + (size_t)t * DDIM);
    float4* r = (float4*)(g_res  + (size_t)t * DDIM);
    int i = threadIdx.x;
    float4 cv = c[i];
    if (stage == 0) {
        q[i] = cv;
        float4 rv = r[i];
        rv.x -= cv.x; rv.y -= cv.y; rv.z -= cv.z; rv.w -= cv.w;
        r[i] = rv;
        __nv_bfloat16 h[4];                         // bf16 shadow for stage-1 GEMM
        h[0] = __float2bfloat16(rv.x); h[1] = __float2bfloat16(rv.y);
        h[2] = __float2bfloat16(rv.z); h[3] = __float2bfloat16(rv.w);
        *((uint2*)(g_res_bf + (size_t)t * DDIM) + i) = *(uint2*)h;
    } else {
        float4 qv = q[i];
        qv.x += cv.x; qv.y += cv.y; qv.z += cv.z; qv.w += cv.w;
        q[i] = qv;
    }
}

// ---------------- launch ----------------------------------------------------
extern "C" void kernel_launch(void* const* d_in, const int* in_sizes, int n_in,
                              void* d_out, int out_size)
{
    const float* x     = (const float*)d_in[0];
    const float* enc_w = (const float*)d_in[1];
    const float* enc_b = (const float*)d_in[2];
    const float* cb    = (const float*)d_in[3];
    const float* dec_w = (const float*)d_in[4];
    const float* dec_b = (const float*)d_in[5];
    float* out = (float*)d_out;

    float *res_p, *q_p;
    __nv_bfloat16 *rb_p, *cbb_p, *ah_p, *al_p, *wh_p, *wl_p;
    cudaGetSymbolAddress((void**)&res_p, g_res);
    cudaGetSymbolAddress((void**)&q_p,   g_qsum);
    cudaGetSymbolAddress((void**)&rb_p,  g_res_bf);
    cudaGetSymbolAddress((void**)&cbb_p, g_cb_bf);
    cudaGetSymbolAddress((void**)&ah_p,  g_a_hi);
    cudaGetSymbolAddress((void**)&al_p,  g_a_lo);
    cudaGetSymbolAddress((void**)&wh_p,  g_w_hi);
    cudaGetSymbolAddress((void**)&wl_p,  g_w_lo);

    cudaFuncSetAttribute(vq_topk, cudaFuncAttributeMaxDynamicSharedMemorySize, VQ_SMEM);
    cudaFuncSetAttribute(gemm3_nt_bias, cudaFuncAttributeMaxDynamicSharedMemorySize, G3_SMEM);

    csq_kernel<<<KCB / 8, 256>>>(cb);
    tobf16_kernel<<<(KCB * DDIM / 4) / 256, 256>>>(cb, cbb_p);

    // encoder: bf16x3 tensor GEMM, emits fp32 z (g_res) + bf16 shadow
    splithl_kernel<<<(DDIM * DDIM / 4) / 256, 256>>>(enc_w, wh_p, wl_p);
    splithl_kernel<<<(TTOK * DDIM / 4) / 256, 256>>>(x, ah_p, al_p);
    gemm3_nt_bias<<<dim3(TTOK / 128, DDIM / 128), 256, G3_SMEM>>>(
        ah_p, al_p, wh_p, wl_p, enc_b, res_p, rb_p);

    // stage 0
    vq_topk<<<TTOK / 128, 256, VQ_SMEM>>>();
    refine_kernel<<<TTOK / 8, 256>>>(cb);
    vq_apply<<<TTOK, 128>>>(cb, 0);   // updates g_res and g_res_bf

    // stage 1
    vq_topk<<<TTOK / 128, 256, VQ_SMEM>>>();
    refine_kernel<<<TTOK / 8, 256>>>(cb);
    vq_apply<<<TTOK, 128>>>(cb, 1);

    // decoder: bf16x3 tensor GEMM on q_sum
    splithl_kernel<<<(DDIM * DDIM / 4) / 256, 256>>>(dec_w, wh_p, wl_p);
    splithl_kernel<<<(TTOK * DDIM / 4) / 256, 256>>>(q_p, ah_p, al_p);
    gemm3_nt_bias<<<dim3(TTOK / 128, DDIM / 128), 256, G3_SMEM>>>(
        ah_p, al_p, wh_p, wl_p, dec_b, out, nullptr);
}